// round 7
// baseline (speedup 1.0000x reference)
#include <cuda_runtime.h>
#include <cstdint>

#define G_SEG   4096
#define D       128
#define DV4     32            // float4 per row (128 floats)
#define NTHR    256
#define ROWG    8             // NTHR / 32 row-groups
#define UNR     8             // rows per warp per outer iteration
#define EPS     1e-5f

__device__ int g_start[G_SEG + 1];

// ---------------------------------------------------------------------------
// Kernel 1: segment boundaries from sorted segment_ids.
// ---------------------------------------------------------------------------
__global__ void seg_bounds_kernel(const int* __restrict__ seg, int n) {
    int i = blockIdx.x * blockDim.x + threadIdx.x;
    if (i > n) return;
    if (i == 0) {
        int s0 = seg[0];
        for (int g = 0; g <= s0; ++g) g_start[g] = 0;
    } else if (i == n) {
        int sl = seg[n - 1];
        for (int g = sl + 1; g <= G_SEG; ++g) g_start[g] = n;
    } else {
        int a = seg[i - 1], b = seg[i];
        if (a != b) {
            for (int g = a + 1; g <= b; ++g) g_start[g] = i;
        }
    }
}

// ---------------------------------------------------------------------------
// Kernel 2: one CTA per segment.
// pass 1: stream rows, 8 independent LDG.128 in flight per warp, accumulate
//         per-dim sum/sumsq in regs.
// single barrier; then EVERY thread reduces the 8 row-group partials for its
// lane and derives affine coeffs A,B in registers (no 2nd barrier).
// pass 2: re-read rows (L2 hit, __ldcs) -> fmaf -> __stcs, unroll 8.
// 4 CTAs/SM (<=64 regs) -> 32 warps, ~128KB/SM in flight.
// ---------------------------------------------------------------------------
__global__ __launch_bounds__(NTHR, 4)
void graphnorm_kernel(const float4* __restrict__ feat,
                      const float4* __restrict__ weight,
                      const float4* __restrict__ bias,
                      const float4* __restrict__ mscale,
                      float4* __restrict__ out) {
    __shared__ float4 redS[NTHR];
    __shared__ float4 redQ[NTHR];

    const int g = blockIdx.x;
    const int s = g_start[g];
    const int e = g_start[g + 1];
    const int cnt = e - s;
    if (cnt <= 0) return;

    const int t    = threadIdx.x;
    const int lane = t & 31;      // which float4 of the row
    const int rg   = t >> 5;      // row-group 0..7

    const float4* base = feat + (size_t)s * DV4;

    float4 sm = make_float4(0.f, 0.f, 0.f, 0.f);
    float4 sq = make_float4(0.f, 0.f, 0.f, 0.f);

    // ---- pass 1: accumulate, 8 rows per warp-iteration ----
    int r = rg;
    const int full_end = cnt - (UNR - 1) * ROWG;   // loop while r + 7*ROWG < cnt
    for (; r < full_end; r += UNR * ROWG) {
        float4 v0 = base[(r + 0 * ROWG) * DV4 + lane];
        float4 v1 = base[(r + 1 * ROWG) * DV4 + lane];
        float4 v2 = base[(r + 2 * ROWG) * DV4 + lane];
        float4 v3 = base[(r + 3 * ROWG) * DV4 + lane];
        float4 v4 = base[(r + 4 * ROWG) * DV4 + lane];
        float4 v5 = base[(r + 5 * ROWG) * DV4 + lane];
        float4 v6 = base[(r + 6 * ROWG) * DV4 + lane];
        float4 v7 = base[(r + 7 * ROWG) * DV4 + lane];

        sm.x += v0.x + v1.x + v2.x + v3.x + v4.x + v5.x + v6.x + v7.x;
        sm.y += v0.y + v1.y + v2.y + v3.y + v4.y + v5.y + v6.y + v7.y;
        sm.z += v0.z + v1.z + v2.z + v3.z + v4.z + v5.z + v6.z + v7.z;
        sm.w += v0.w + v1.w + v2.w + v3.w + v4.w + v5.w + v6.w + v7.w;

        sq.x = fmaf(v0.x, v0.x, sq.x); sq.x = fmaf(v1.x, v1.x, sq.x);
        sq.x = fmaf(v2.x, v2.x, sq.x); sq.x = fmaf(v3.x, v3.x, sq.x);
        sq.x = fmaf(v4.x, v4.x, sq.x); sq.x = fmaf(v5.x, v5.x, sq.x);
        sq.x = fmaf(v6.x, v6.x, sq.x); sq.x = fmaf(v7.x, v7.x, sq.x);

        sq.y = fmaf(v0.y, v0.y, sq.y); sq.y = fmaf(v1.y, v1.y, sq.y);
        sq.y = fmaf(v2.y, v2.y, sq.y); sq.y = fmaf(v3.y, v3.y, sq.y);
        sq.y = fmaf(v4.y, v4.y, sq.y); sq.y = fmaf(v5.y, v5.y, sq.y);
        sq.y = fmaf(v6.y, v6.y, sq.y); sq.y = fmaf(v7.y, v7.y, sq.y);

        sq.z = fmaf(v0.z, v0.z, sq.z); sq.z = fmaf(v1.z, v1.z, sq.z);
        sq.z = fmaf(v2.z, v2.z, sq.z); sq.z = fmaf(v3.z, v3.z, sq.z);
        sq.z = fmaf(v4.z, v4.z, sq.z); sq.z = fmaf(v5.z, v5.z, sq.z);
        sq.z = fmaf(v6.z, v6.z, sq.z); sq.z = fmaf(v7.z, v7.z, sq.z);

        sq.w = fmaf(v0.w, v0.w, sq.w); sq.w = fmaf(v1.w, v1.w, sq.w);
        sq.w = fmaf(v2.w, v2.w, sq.w); sq.w = fmaf(v3.w, v3.w, sq.w);
        sq.w = fmaf(v4.w, v4.w, sq.w); sq.w = fmaf(v5.w, v5.w, sq.w);
        sq.w = fmaf(v6.w, v6.w, sq.w); sq.w = fmaf(v7.w, v7.w, sq.w);
    }
    // remainder
    for (; r < cnt; r += ROWG) {
        float4 v = base[r * DV4 + lane];
        sm.x += v.x; sm.y += v.y; sm.z += v.z; sm.w += v.w;
        sq.x = fmaf(v.x, v.x, sq.x);
        sq.y = fmaf(v.y, v.y, sq.y);
        sq.z = fmaf(v.z, v.z, sq.z);
        sq.w = fmaf(v.w, v.w, sq.w);
    }

    redS[t] = sm;
    redQ[t] = sq;
    __syncthreads();

    // ---- every thread reduces its lane's 8 partials + computes A,B ----
    float4 S = redS[lane], Q = redQ[lane];
    #pragma unroll
    for (int j = 1; j < ROWG; ++j) {
        float4 a = redS[j * 32 + lane], b = redQ[j * 32 + lane];
        S.x += a.x; S.y += a.y; S.z += a.z; S.w += a.w;
        Q.x += b.x; Q.y += b.y; Q.z += b.z; Q.w += b.w;
    }

    const float ic = 1.0f / (float)cnt;
    const float4 w  = weight[lane];
    const float4 b4 = bias[lane];
    const float4 sc = mscale[lane];
    float4 A, B;
    {
        float m = S.x * ic, q = Q.x * ic;
        float var = q - m * m * sc.x * (2.0f - sc.x);
        A.x = w.x * rsqrtf(var + EPS);
        B.x = b4.x - m * sc.x * A.x;
    }
    {
        float m = S.y * ic, q = Q.y * ic;
        float var = q - m * m * sc.y * (2.0f - sc.y);
        A.y = w.y * rsqrtf(var + EPS);
        B.y = b4.y - m * sc.y * A.y;
    }
    {
        float m = S.z * ic, q = Q.z * ic;
        float var = q - m * m * sc.z * (2.0f - sc.z);
        A.z = w.z * rsqrtf(var + EPS);
        B.z = b4.z - m * sc.z * A.z;
    }
    {
        float m = S.w * ic, q = Q.w * ic;
        float var = q - m * m * sc.w * (2.0f - sc.w);
        A.w = w.w * rsqrtf(var + EPS);
        B.w = b4.w - m * sc.w * A.w;
    }

    float4* obase = out + (size_t)s * DV4;

    // ---- pass 2: L2 re-read -> affine -> streaming store, unroll 8 ----
    r = rg;
    for (; r < full_end; r += UNR * ROWG) {
        float4 v0 = __ldcs(&base[(r + 0 * ROWG) * DV4 + lane]);
        float4 v1 = __ldcs(&base[(r + 1 * ROWG) * DV4 + lane]);
        float4 v2 = __ldcs(&base[(r + 2 * ROWG) * DV4 + lane]);
        float4 v3 = __ldcs(&base[(r + 3 * ROWG) * DV4 + lane]);
        float4 v4 = __ldcs(&base[(r + 4 * ROWG) * DV4 + lane]);
        float4 v5 = __ldcs(&base[(r + 5 * ROWG) * DV4 + lane]);
        float4 v6 = __ldcs(&base[(r + 6 * ROWG) * DV4 + lane]);
        float4 v7 = __ldcs(&base[(r + 7 * ROWG) * DV4 + lane]);

        float4 o;
        o.x = fmaf(v0.x, A.x, B.x); o.y = fmaf(v0.y, A.y, B.y);
        o.z = fmaf(v0.z, A.z, B.z); o.w = fmaf(v0.w, A.w, B.w);
        __stcs(&obase[(r + 0 * ROWG) * DV4 + lane], o);
        o.x = fmaf(v1.x, A.x, B.x); o.y = fmaf(v1.y, A.y, B.y);
        o.z = fmaf(v1.z, A.z, B.z); o.w = fmaf(v1.w, A.w, B.w);
        __stcs(&obase[(r + 1 * ROWG) * DV4 + lane], o);
        o.x = fmaf(v2.x, A.x, B.x); o.y = fmaf(v2.y, A.y, B.y);
        o.z = fmaf(v2.z, A.z, B.z); o.w = fmaf(v2.w, A.w, B.w);
        __stcs(&obase[(r + 2 * ROWG) * DV4 + lane], o);
        o.x = fmaf(v3.x, A.x, B.x); o.y = fmaf(v3.y, A.y, B.y);
        o.z = fmaf(v3.z, A.z, B.z); o.w = fmaf(v3.w, A.w, B.w);
        __stcs(&obase[(r + 3 * ROWG) * DV4 + lane], o);
        o.x = fmaf(v4.x, A.x, B.x); o.y = fmaf(v4.y, A.y, B.y);
        o.z = fmaf(v4.z, A.z, B.z); o.w = fmaf(v4.w, A.w, B.w);
        __stcs(&obase[(r + 4 * ROWG) * DV4 + lane], o);
        o.x = fmaf(v5.x, A.x, B.x); o.y = fmaf(v5.y, A.y, B.y);
        o.z = fmaf(v5.z, A.z, B.z); o.w = fmaf(v5.w, A.w, B.w);
        __stcs(&obase[(r + 5 * ROWG) * DV4 + lane], o);
        o.x = fmaf(v6.x, A.x, B.x); o.y = fmaf(v6.y, A.y, B.y);
        o.z = fmaf(v6.z, A.z, B.z); o.w = fmaf(v6.w, A.w, B.w);
        __stcs(&obase[(r + 6 * ROWG) * DV4 + lane], o);
        o.x = fmaf(v7.x, A.x, B.x); o.y = fmaf(v7.y, A.y, B.y);
        o.z = fmaf(v7.z, A.z, B.z); o.w = fmaf(v7.w, A.w, B.w);
        __stcs(&obase[(r + 7 * ROWG) * DV4 + lane], o);
    }
    for (; r < cnt; r += ROWG) {
        float4 v = __ldcs(&base[r * DV4 + lane]);
        float4 o;
        o.x = fmaf(v.x, A.x, B.x);
        o.y = fmaf(v.y, A.y, B.y);
        o.z = fmaf(v.z, A.z, B.z);
        o.w = fmaf(v.w, A.w, B.w);
        __stcs(&obase[r * DV4 + lane], o);
    }
}

// ---------------------------------------------------------------------------
// Launch
// inputs: [0] features (N*D f32), [1] segment_ids (N i32), [2] num_graphs,
//         [3] weight (D), [4] bias (D), [5] mean_scale (D)
// ---------------------------------------------------------------------------
extern "C" void kernel_launch(void* const* d_in, const int* in_sizes, int n_in,
                              void* d_out, int out_size) {
    const float* feat = (const float*)d_in[0];
    const int*   seg  = (const int*)d_in[1];
    const float* w    = (const float*)d_in[3];
    const float* b    = (const float*)d_in[4];
    const float* ms   = (const float*)d_in[5];
    const int n = in_sizes[1];   // number of rows

    {
        int threads = 256;
        int blocks  = (n + 1 + threads - 1) / threads;
        seg_bounds_kernel<<<blocks, threads>>>(seg, n);
    }

    graphnorm_kernel<<<G_SEG, NTHR>>>(
        (const float4*)feat, (const float4*)w, (const float4*)b,
        (const float4*)ms, (float4*)d_out);
}

// round 10
// speedup vs baseline: 1.0745x; 1.0745x over previous
#include <cuda_runtime.h>
#include <cstdint>

#define G_SEG   4096
#define D       128
#define DV4     32            // float4 per row (128 floats)
#define NTHR    256
#define ROWG    8             // NTHR / 32 row-groups
#define UNR     8             // rows per warp per outer iteration
#define EPS     1e-5f

__device__ int g_start[G_SEG + 1];

// ---------------------------------------------------------------------------
// Kernel 1: segment boundaries from sorted segment_ids.
// ---------------------------------------------------------------------------
__global__ void seg_bounds_kernel(const int* __restrict__ seg, int n) {
    int i = blockIdx.x * blockDim.x + threadIdx.x;
    if (i > n) return;
    if (i == 0) {
        int s0 = seg[0];
        for (int g = 0; g <= s0; ++g) g_start[g] = 0;
    } else if (i == n) {
        int sl = seg[n - 1];
        for (int g = sl + 1; g <= G_SEG; ++g) g_start[g] = n;
    } else {
        int a = seg[i - 1], b = seg[i];
        if (a != b) {
            for (int g = a + 1; g <= b; ++g) g_start[g] = i;
        }
    }
}

// ---------------------------------------------------------------------------
// Kernel 2: one CTA per segment, 3 CTAs/SM (R6 config).
// pass 1: stream rows, 8 independent LDG.128 in flight per warp.
// Before the reduction barrier: PREFETCH the first pass-2 batch (__ldcs, L2
// hits) so the memory pipe stays busy through barrier + reduce + A/B math.
// pass 2: consume prefetched batch, then steady unroll-8 loop.
// ---------------------------------------------------------------------------
__global__ __launch_bounds__(NTHR, 3)
void graphnorm_kernel(const float4* __restrict__ feat,
                      const float4* __restrict__ weight,
                      const float4* __restrict__ bias,
                      const float4* __restrict__ mscale,
                      float4* __restrict__ out) {
    __shared__ float4 redS[NTHR];
    __shared__ float4 redQ[NTHR];

    const int g = blockIdx.x;
    const int s = g_start[g];
    const int e = g_start[g + 1];
    const int cnt = e - s;
    if (cnt <= 0) return;

    const int t    = threadIdx.x;
    const int lane = t & 31;      // which float4 of the row
    const int rg   = t >> 5;      // row-group 0..7

    const float4* base = feat + (size_t)s * DV4;

    float4 sm = make_float4(0.f, 0.f, 0.f, 0.f);
    float4 sq = make_float4(0.f, 0.f, 0.f, 0.f);

    // ---- pass 1: accumulate, 8 rows per warp-iteration ----
    int r = rg;
    const int full_end = cnt - (UNR - 1) * ROWG;   // loop while r + 7*ROWG < cnt
    for (; r < full_end; r += UNR * ROWG) {
        float4 v0 = base[(r + 0 * ROWG) * DV4 + lane];
        float4 v1 = base[(r + 1 * ROWG) * DV4 + lane];
        float4 v2 = base[(r + 2 * ROWG) * DV4 + lane];
        float4 v3 = base[(r + 3 * ROWG) * DV4 + lane];
        float4 v4 = base[(r + 4 * ROWG) * DV4 + lane];
        float4 v5 = base[(r + 5 * ROWG) * DV4 + lane];
        float4 v6 = base[(r + 6 * ROWG) * DV4 + lane];
        float4 v7 = base[(r + 7 * ROWG) * DV4 + lane];

        sm.x += v0.x + v1.x + v2.x + v3.x + v4.x + v5.x + v6.x + v7.x;
        sm.y += v0.y + v1.y + v2.y + v3.y + v4.y + v5.y + v6.y + v7.y;
        sm.z += v0.z + v1.z + v2.z + v3.z + v4.z + v5.z + v6.z + v7.z;
        sm.w += v0.w + v1.w + v2.w + v3.w + v4.w + v5.w + v6.w + v7.w;

        sq.x = fmaf(v0.x, v0.x, sq.x); sq.x = fmaf(v1.x, v1.x, sq.x);
        sq.x = fmaf(v2.x, v2.x, sq.x); sq.x = fmaf(v3.x, v3.x, sq.x);
        sq.x = fmaf(v4.x, v4.x, sq.x); sq.x = fmaf(v5.x, v5.x, sq.x);
        sq.x = fmaf(v6.x, v6.x, sq.x); sq.x = fmaf(v7.x, v7.x, sq.x);

        sq.y = fmaf(v0.y, v0.y, sq.y); sq.y = fmaf(v1.y, v1.y, sq.y);
        sq.y = fmaf(v2.y, v2.y, sq.y); sq.y = fmaf(v3.y, v3.y, sq.y);
        sq.y = fmaf(v4.y, v4.y, sq.y); sq.y = fmaf(v5.y, v5.y, sq.y);
        sq.y = fmaf(v6.y, v6.y, sq.y); sq.y = fmaf(v7.y, v7.y, sq.y);

        sq.z = fmaf(v0.z, v0.z, sq.z); sq.z = fmaf(v1.z, v1.z, sq.z);
        sq.z = fmaf(v2.z, v2.z, sq.z); sq.z = fmaf(v3.z, v3.z, sq.z);
        sq.z = fmaf(v4.z, v4.z, sq.z); sq.z = fmaf(v5.z, v5.z, sq.z);
        sq.z = fmaf(v6.z, v6.z, sq.z); sq.z = fmaf(v7.z, v7.z, sq.z);

        sq.w = fmaf(v0.w, v0.w, sq.w); sq.w = fmaf(v1.w, v1.w, sq.w);
        sq.w = fmaf(v2.w, v2.w, sq.w); sq.w = fmaf(v3.w, v3.w, sq.w);
        sq.w = fmaf(v4.w, v4.w, sq.w); sq.w = fmaf(v5.w, v5.w, sq.w);
        sq.w = fmaf(v6.w, v6.w, sq.w); sq.w = fmaf(v7.w, v7.w, sq.w);
    }
    // remainder
    for (; r < cnt; r += ROWG) {
        float4 v = base[r * DV4 + lane];
        sm.x += v.x; sm.y += v.y; sm.z += v.z; sm.w += v.w;
        sq.x = fmaf(v.x, v.x, sq.x);
        sq.y = fmaf(v.y, v.y, sq.y);
        sq.z = fmaf(v.z, v.z, sq.z);
        sq.w = fmaf(v.w, v.w, sq.w);
    }

    // ---- prefetch first pass-2 batch BEFORE the barrier (L2 hits) ----
    // These loads do not depend on the reduction; they cover the barrier +
    // reduce + A/B latency with memory work.
    const bool has_full = (rg < full_end);   // first batch of the unrolled loop exists
    float4 p0, p1, p2, p3, p4, p5, p6, p7;
    if (has_full) {
        p0 = __ldcs(&base[(rg + 0 * ROWG) * DV4 + lane]);
        p1 = __ldcs(&base[(rg + 1 * ROWG) * DV4 + lane]);
        p2 = __ldcs(&base[(rg + 2 * ROWG) * DV4 + lane]);
        p3 = __ldcs(&base[(rg + 3 * ROWG) * DV4 + lane]);
        p4 = __ldcs(&base[(rg + 4 * ROWG) * DV4 + lane]);
        p5 = __ldcs(&base[(rg + 5 * ROWG) * DV4 + lane]);
        p6 = __ldcs(&base[(rg + 6 * ROWG) * DV4 + lane]);
        p7 = __ldcs(&base[(rg + 7 * ROWG) * DV4 + lane]);
    }

    redS[t] = sm;
    redQ[t] = sq;
    __syncthreads();

    // ---- every thread reduces its lane's 8 partials + computes A,B ----
    float4 S = redS[lane], Q = redQ[lane];
    #pragma unroll
    for (int j = 1; j < ROWG; ++j) {
        float4 a = redS[j * 32 + lane], b = redQ[j * 32 + lane];
        S.x += a.x; S.y += a.y; S.z += a.z; S.w += a.w;
        Q.x += b.x; Q.y += b.y; Q.z += b.z; Q.w += b.w;
    }

    const float ic = 1.0f / (float)cnt;
    const float4 w  = weight[lane];
    const float4 b4 = bias[lane];
    const float4 sc = mscale[lane];
    float4 A, B;
    {
        float m = S.x * ic, q = Q.x * ic;
        float var = q - m * m * sc.x * (2.0f - sc.x);
        A.x = w.x * rsqrtf(var + EPS);
        B.x = b4.x - m * sc.x * A.x;
    }
    {
        float m = S.y * ic, q = Q.y * ic;
        float var = q - m * m * sc.y * (2.0f - sc.y);
        A.y = w.y * rsqrtf(var + EPS);
        B.y = b4.y - m * sc.y * A.y;
    }
    {
        float m = S.z * ic, q = Q.z * ic;
        float var = q - m * m * sc.z * (2.0f - sc.z);
        A.z = w.z * rsqrtf(var + EPS);
        B.z = b4.z - m * sc.z * A.z;
    }
    {
        float m = S.w * ic, q = Q.w * ic;
        float var = q - m * m * sc.w * (2.0f - sc.w);
        A.w = w.w * rsqrtf(var + EPS);
        B.w = b4.w - m * sc.w * A.w;
    }

    float4* obase = out + (size_t)s * DV4;

    // ---- pass 2: consume prefetched batch, then steady loop ----
    r = rg;
    if (has_full) {
        float4 o;
        o.x = fmaf(p0.x, A.x, B.x); o.y = fmaf(p0.y, A.y, B.y);
        o.z = fmaf(p0.z, A.z, B.z); o.w = fmaf(p0.w, A.w, B.w);
        __stcs(&obase[(r + 0 * ROWG) * DV4 + lane], o);
        o.x = fmaf(p1.x, A.x, B.x); o.y = fmaf(p1.y, A.y, B.y);
        o.z = fmaf(p1.z, A.z, B.z); o.w = fmaf(p1.w, A.w, B.w);
        __stcs(&obase[(r + 1 * ROWG) * DV4 + lane], o);
        o.x = fmaf(p2.x, A.x, B.x); o.y = fmaf(p2.y, A.y, B.y);
        o.z = fmaf(p2.z, A.z, B.z); o.w = fmaf(p2.w, A.w, B.w);
        __stcs(&obase[(r + 2 * ROWG) * DV4 + lane], o);
        o.x = fmaf(p3.x, A.x, B.x); o.y = fmaf(p3.y, A.y, B.y);
        o.z = fmaf(p3.z, A.z, B.z); o.w = fmaf(p3.w, A.w, B.w);
        __stcs(&obase[(r + 3 * ROWG) * DV4 + lane], o);
        o.x = fmaf(p4.x, A.x, B.x); o.y = fmaf(p4.y, A.y, B.y);
        o.z = fmaf(p4.z, A.z, B.z); o.w = fmaf(p4.w, A.w, B.w);
        __stcs(&obase[(r + 4 * ROWG) * DV4 + lane], o);
        o.x = fmaf(p5.x, A.x, B.x); o.y = fmaf(p5.y, A.y, B.y);
        o.z = fmaf(p5.z, A.z, B.z); o.w = fmaf(p5.w, A.w, B.w);
        __stcs(&obase[(r + 5 * ROWG) * DV4 + lane], o);
        o.x = fmaf(p6.x, A.x, B.x); o.y = fmaf(p6.y, A.y, B.y);
        o.z = fmaf(p6.z, A.z, B.z); o.w = fmaf(p6.w, A.w, B.w);
        __stcs(&obase[(r + 6 * ROWG) * DV4 + lane], o);
        o.x = fmaf(p7.x, A.x, B.x); o.y = fmaf(p7.y, A.y, B.y);
        o.z = fmaf(p7.z, A.z, B.z); o.w = fmaf(p7.w, A.w, B.w);
        __stcs(&obase[(r + 7 * ROWG) * DV4 + lane], o);
        r += UNR * ROWG;
    }
    for (; r < full_end; r += UNR * ROWG) {
        float4 v0 = __ldcs(&base[(r + 0 * ROWG) * DV4 + lane]);
        float4 v1 = __ldcs(&base[(r + 1 * ROWG) * DV4 + lane]);
        float4 v2 = __ldcs(&base[(r + 2 * ROWG) * DV4 + lane]);
        float4 v3 = __ldcs(&base[(r + 3 * ROWG) * DV4 + lane]);
        float4 v4 = __ldcs(&base[(r + 4 * ROWG) * DV4 + lane]);
        float4 v5 = __ldcs(&base[(r + 5 * ROWG) * DV4 + lane]);
        float4 v6 = __ldcs(&base[(r + 6 * ROWG) * DV4 + lane]);
        float4 v7 = __ldcs(&base[(r + 7 * ROWG) * DV4 + lane]);

        float4 o;
        o.x = fmaf(v0.x, A.x, B.x); o.y = fmaf(v0.y, A.y, B.y);
        o.z = fmaf(v0.z, A.z, B.z); o.w = fmaf(v0.w, A.w, B.w);
        __stcs(&obase[(r + 0 * ROWG) * DV4 + lane], o);
        o.x = fmaf(v1.x, A.x, B.x); o.y = fmaf(v1.y, A.y, B.y);
        o.z = fmaf(v1.z, A.z, B.z); o.w = fmaf(v1.w, A.w, B.w);
        __stcs(&obase[(r + 1 * ROWG) * DV4 + lane], o);
        o.x = fmaf(v2.x, A.x, B.x); o.y = fmaf(v2.y, A.y, B.y);
        o.z = fmaf(v2.z, A.z, B.z); o.w = fmaf(v2.w, A.w, B.w);
        __stcs(&obase[(r + 2 * ROWG) * DV4 + lane], o);
        o.x = fmaf(v3.x, A.x, B.x); o.y = fmaf(v3.y, A.y, B.y);
        o.z = fmaf(v3.z, A.z, B.z); o.w = fmaf(v3.w, A.w, B.w);
        __stcs(&obase[(r + 3 * ROWG) * DV4 + lane], o);
        o.x = fmaf(v4.x, A.x, B.x); o.y = fmaf(v4.y, A.y, B.y);
        o.z = fmaf(v4.z, A.z, B.z); o.w = fmaf(v4.w, A.w, B.w);
        __stcs(&obase[(r + 4 * ROWG) * DV4 + lane], o);
        o.x = fmaf(v5.x, A.x, B.x); o.y = fmaf(v5.y, A.y, B.y);
        o.z = fmaf(v5.z, A.z, B.z); o.w = fmaf(v5.w, A.w, B.w);
        __stcs(&obase[(r + 5 * ROWG) * DV4 + lane], o);
        o.x = fmaf(v6.x, A.x, B.x); o.y = fmaf(v6.y, A.y, B.y);
        o.z = fmaf(v6.z, A.z, B.z); o.w = fmaf(v6.w, A.w, B.w);
        __stcs(&obase[(r + 6 * ROWG) * DV4 + lane], o);
        o.x = fmaf(v7.x, A.x, B.x); o.y = fmaf(v7.y, A.y, B.y);
        o.z = fmaf(v7.z, A.z, B.z); o.w = fmaf(v7.w, A.w, B.w);
        __stcs(&obase[(r + 7 * ROWG) * DV4 + lane], o);
    }
    for (; r < cnt; r += ROWG) {
        float4 v = __ldcs(&base[r * DV4 + lane]);
        float4 o;
        o.x = fmaf(v.x, A.x, B.x);
        o.y = fmaf(v.y, A.y, B.y);
        o.z = fmaf(v.z, A.z, B.z);
        o.w = fmaf(v.w, A.w, B.w);
        __stcs(&obase[r * DV4 + lane], o);
    }
}

// ---------------------------------------------------------------------------
// Launch
// inputs: [0] features (N*D f32), [1] segment_ids (N i32), [2] num_graphs,
//         [3] weight (D), [4] bias (D), [5] mean_scale (D)
// ---------------------------------------------------------------------------
extern "C" void kernel_launch(void* const* d_in, const int* in_sizes, int n_in,
                              void* d_out, int out_size) {
    const float* feat = (const float*)d_in[0];
    const int*   seg  = (const int*)d_in[1];
    const float* w    = (const float*)d_in[3];
    const float* b    = (const float*)d_in[4];
    const float* ms   = (const float*)d_in[5];
    const int n = in_sizes[1];   // number of rows

    {
        int threads = 256;
        int blocks  = (n + 1 + threads - 1) / threads;
        seg_bounds_kernel<<<blocks, threads>>>(seg, n);
    }

    graphnorm_kernel<<<G_SEG, NTHR>>>(
        (const float4*)feat, (const float4*)w, (const float4*)b,
        (const float4*)ms, (float4*)d_out);
}